// round 3
// baseline (speedup 1.0000x reference)
#include <cuda_runtime.h>
#include <math_constants.h>

#define BB   2
#define NN   1024
#define CC   768
#define HH   12
#define HD   64
#define HIDN 64

// ---------------- scratch (static device arrays; no allocation) -------------
__device__ float g_q[BB*HH*NN*HD];                 // 6 MB
__device__ float g_k[BB*HH*NN*HD];                 // 6 MB
__device__ float g_v[BB*HH*NN*HD];                 // 6 MB
__device__ float g_bias[(size_t)BB*HH*NN*NN];      // 100.7 MB
__device__ float g_att[BB*NN*CC];                  // 6 MB
__device__ float g_inv[BB*3];

// ---------------- 1) per-batch per-dim coordinate range ---------------------
__global__ void range_kernel(const float* __restrict__ coords)
{
    int b = blockIdx.x, t = threadIdx.x;
    float mx[3] = {-1e30f, -1e30f, -1e30f};
    float mn[3] = { 1e30f,  1e30f,  1e30f};
    for (int n = t; n < NN; n += 256) {
        const float* c = coords + ((size_t)b*NN + n)*3;
        #pragma unroll
        for (int d = 0; d < 3; d++) {
            float v = c[d];
            mx[d] = fmaxf(mx[d], v);
            mn[d] = fminf(mn[d], v);
        }
    }
    __shared__ float smx[3][256], smn[3][256];
    #pragma unroll
    for (int d = 0; d < 3; d++) { smx[d][t] = mx[d]; smn[d][t] = mn[d]; }
    __syncthreads();
    for (int s = 128; s > 0; s >>= 1) {
        if (t < s) {
            #pragma unroll
            for (int d = 0; d < 3; d++) {
                smx[d][t] = fmaxf(smx[d][t], smx[d][t+s]);
                smn[d][t] = fminf(smn[d][t], smn[d][t+s]);
            }
        }
        __syncthreads();
    }
    if (t < 3) g_inv[b*3 + t] = 1.0f / ((smx[t][0] - smn[t][0]) + 1e-6f);
}

// ---------------- 2) SGEMM: C[m][o] = sum_k A[m][k] * W[o][k] ---------------
// mode 0: A = x (2048x768), W = qkv_w (2304x768), scatter into g_q/g_k/g_v
// mode 1: A = g_att (2048x768), W = proj_w (768x768), out = d_out (+ proj_b)
__global__ void __launch_bounds__(256) sgemm_kernel(
    const float* __restrict__ Ain, const float* __restrict__ W,
    const float* __restrict__ bias, float* __restrict__ out, int mode)
{
    __shared__ float As[16*132];
    __shared__ float Bs[16*132];

    const float* A = (mode == 0) ? Ain : g_att;
    const int tid = threadIdx.x;
    const int m0 = blockIdx.y * 128, n0 = blockIdx.x * 128;
    const int rb = (tid >> 4) * 8, cb = (tid & 15) * 8;

    float acc[8][8];
    #pragma unroll
    for (int i = 0; i < 8; i++)
        #pragma unroll
        for (int j = 0; j < 8; j++) acc[i][j] = 0.f;

    for (int k0 = 0; k0 < 768; k0 += 16) {
        #pragma unroll
        for (int f = tid; f < 512; f += 256) {
            int row = f >> 2, kc = (f & 3) << 2;
            float4 a = *(const float4*)(A + (size_t)(m0+row)*768 + k0 + kc);
            As[(kc+0)*132 + row] = a.x;
            As[(kc+1)*132 + row] = a.y;
            As[(kc+2)*132 + row] = a.z;
            As[(kc+3)*132 + row] = a.w;
            float4 w = *(const float4*)(W + (size_t)(n0+row)*768 + k0 + kc);
            Bs[(kc+0)*132 + row] = w.x;
            Bs[(kc+1)*132 + row] = w.y;
            Bs[(kc+2)*132 + row] = w.z;
            Bs[(kc+3)*132 + row] = w.w;
        }
        __syncthreads();
        #pragma unroll
        for (int kk = 0; kk < 16; kk++) {
            float a[8], b[8];
            float4 t0 = *(float4*)&As[kk*132 + rb];
            float4 t1 = *(float4*)&As[kk*132 + rb + 4];
            a[0]=t0.x; a[1]=t0.y; a[2]=t0.z; a[3]=t0.w;
            a[4]=t1.x; a[5]=t1.y; a[6]=t1.z; a[7]=t1.w;
            float4 u0 = *(float4*)&Bs[kk*132 + cb];
            float4 u1 = *(float4*)&Bs[kk*132 + cb + 4];
            b[0]=u0.x; b[1]=u0.y; b[2]=u0.z; b[3]=u0.w;
            b[4]=u1.x; b[5]=u1.y; b[6]=u1.z; b[7]=u1.w;
            #pragma unroll
            for (int i = 0; i < 8; i++)
                #pragma unroll
                for (int j = 0; j < 8; j++)
                    acc[i][j] = fmaf(a[i], b[j], acc[i][j]);
        }
        __syncthreads();
    }

    if (mode == 0) {
        #pragma unroll
        for (int i = 0; i < 8; i++) {
            int m = m0 + rb + i;
            int bb = m >> 10, n = m & 1023;
            #pragma unroll
            for (int j = 0; j < 8; j += 4) {
                int o = n0 + cb + j;
                int part = o / 768;
                int within = o - part * 768;
                int h = within >> 6, d = within & 63;
                float* dst = (part == 0 ? g_q : (part == 1 ? g_k : g_v))
                           + (((size_t)bb*HH + h)*NN + n)*HD + d;
                *(float4*)dst = make_float4(acc[i][j], acc[i][j+1], acc[i][j+2], acc[i][j+3]);
            }
        }
    } else {
        #pragma unroll
        for (int i = 0; i < 8; i++) {
            int m = m0 + rb + i;
            #pragma unroll
            for (int j = 0; j < 8; j += 4) {
                int o = n0 + cb + j;
                float4 bv = *(const float4*)(bias + o);
                *(float4*)(out + (size_t)m*768 + o) =
                    make_float4(acc[i][j]+bv.x, acc[i][j+1]+bv.y,
                                acc[i][j+2]+bv.z, acc[i][j+3]+bv.w);
            }
        }
    }
}

// ---------------- 3) relative-position bias MLP -----------------------------
__global__ void __launch_bounds__(256) bias_kernel(
    const float* __restrict__ coords, const float* __restrict__ w1,
    const float* __restrict__ b1, const float* __restrict__ w2,
    const float* __restrict__ b2)
{
    __shared__ float s_w1[HIDN*3], s_b1[HIDN], s_w2t[HIDN*HH], s_b2[HH], s_inv[3];
    int tid = threadIdx.x;
    int b = blockIdx.y;
    if (tid < HIDN*3) s_w1[tid] = w1[tid];
    if (tid < HIDN)   s_b1[tid] = b1[tid];
    if (tid < HH)     s_b2[tid] = b2[tid];
    if (tid < 3)      s_inv[tid] = g_inv[b*3 + tid];
    for (int idx = tid; idx < HH*HIDN; idx += 256) {
        int h = idx >> 6, k = idx & 63;
        s_w2t[k*HH + h] = w2[idx];
    }
    __syncthreads();

    int idx = blockIdx.x * 256 + tid;
    int i = idx >> 10, j = idx & 1023;
    const float* ci = coords + ((size_t)b*NN + i)*3;
    const float* cj = coords + ((size_t)b*NN + j)*3;
    float r0 = (ci[0] - cj[0]) * s_inv[0];
    float r1 = (ci[1] - cj[1]) * s_inv[1];
    float r2 = (ci[2] - cj[2]) * s_inv[2];

    float acc[HH];
    #pragma unroll
    for (int h = 0; h < HH; h++) acc[h] = s_b2[h];

    #pragma unroll 8
    for (int k = 0; k < HIDN; k++) {
        float hv = fmaf(s_w1[k*3+0], r0,
                   fmaf(s_w1[k*3+1], r1,
                   fmaf(s_w1[k*3+2], r2, s_b1[k])));
        hv = fmaxf(hv, 0.f);
        #pragma unroll
        for (int h = 0; h < HH; h++)
            acc[h] = fmaf(s_w2t[k*HH + h], hv, acc[h]);
    }

    size_t base = (((size_t)b*HH)*NN + i)*NN + j;
    #pragma unroll
    for (int h = 0; h < HH; h++)
        g_bias[base + (size_t)h*NN*NN] = acc[h];
}

// ---------------- 4) flash attention with fused bias ------------------------
// grid (N/64, H, B), 256 threads (16x16), 64x64 tiles, online softmax.
// smem: Qs[64][64] | KsPt[64][65] (K transposed, reused as P^T) | Vs[64][64]
__global__ void __launch_bounds__(256) attn_kernel()
{
    extern __shared__ float sm[];
    float* Qs   = sm;                 // 4096 floats
    float* KsPt = sm + 4096;          // 4160 floats (pitch 65)
    float* Vs   = sm + 4096 + 4160;   // 4096 floats

    const int tid = threadIdx.x;
    const int tx = tid & 15, ty = tid >> 4;
    const int i0 = blockIdx.x * 64;
    const int h  = blockIdx.y;
    const int b  = blockIdx.z;

    const size_t hoff = (((size_t)b*HH + h)*NN)*HD;
    const float* qp = g_q + hoff;
    const float* kp = g_k + hoff;
    const float* vp = g_v + hoff;
    const float* biasp = g_bias + (((size_t)b*HH + h)*NN + i0)*NN;

    // load Q tile [64 rows][64 d], natural layout
    #pragma unroll
    for (int f = tid; f < 1024; f += 256) {
        int i = f >> 4, d4 = (f & 15) << 2;
        *(float4*)&Qs[i*64 + d4] = *(const float4*)&qp[(size_t)(i0+i)*HD + d4];
    }

    float m[4], l[4], O[4][4];
    #pragma unroll
    for (int rr = 0; rr < 4; rr++) {
        m[rr] = -1e30f; l[rr] = 0.f;
        #pragma unroll
        for (int cc = 0; cc < 4; cc++) O[rr][cc] = 0.f;
    }
    const float scale = 0.125f;   // 64^-0.5

    for (int jt = 0; jt < 16; jt++) {
        int j0 = jt * 64;
        __syncthreads();   // previous iter done with KsPt/Vs (also fences Q load on iter 0)
        #pragma unroll
        for (int f = tid; f < 1024; f += 256) {
            int j = f >> 4, d4 = (f & 15) << 2;
            float4 kv = *(const float4*)&kp[(size_t)(j0+j)*HD + d4];
            KsPt[(d4+0)*65 + j] = kv.x;
            KsPt[(d4+1)*65 + j] = kv.y;
            KsPt[(d4+2)*65 + j] = kv.z;
            KsPt[(d4+3)*65 + j] = kv.w;
            *(float4*)&Vs[j*64 + d4] = *(const float4*)&vp[(size_t)(j0+j)*HD + d4];
        }
        __syncthreads();

        // S = Q K^T
        float acc[4][4];
        #pragma unroll
        for (int rr = 0; rr < 4; rr++)
            #pragma unroll
            for (int cc = 0; cc < 4; cc++) acc[rr][cc] = 0.f;

        #pragma unroll 8
        for (int d = 0; d < 64; d++) {
            float aq[4], bk[4];
            #pragma unroll
            for (int rr = 0; rr < 4; rr++) aq[rr] = Qs[(4*ty+rr)*64 + d];
            #pragma unroll
            for (int cc = 0; cc < 4; cc++) bk[cc] = KsPt[d*65 + 4*tx + cc];
            #pragma unroll
            for (int rr = 0; rr < 4; rr++)
                #pragma unroll
                for (int cc = 0; cc < 4; cc++)
                    acc[rr][cc] = fmaf(aq[rr], bk[cc], acc[rr][cc]);
        }

        float S[4][4];
        #pragma unroll
        for (int rr = 0; rr < 4; rr++) {
            float4 bb = *(const float4*)&biasp[(size_t)(4*ty+rr)*NN + j0 + 4*tx];
            S[rr][0] = fmaf(acc[rr][0], scale, bb.x);
            S[rr][1] = fmaf(acc[rr][1], scale, bb.y);
            S[rr][2] = fmaf(acc[rr][2], scale, bb.z);
            S[rr][3] = fmaf(acc[rr][3], scale, bb.w);
        }

        // online softmax update (row stats replicated across the 16 tx lanes)
        #pragma unroll
        for (int rr = 0; rr < 4; rr++) {
            float tmax = fmaxf(fmaxf(S[rr][0], S[rr][1]), fmaxf(S[rr][2], S[rr][3]));
            #pragma unroll
            for (int off = 1; off < 16; off <<= 1)
                tmax = fmaxf(tmax, __shfl_xor_sync(0xffffffffu, tmax, off));
            float mnew  = fmaxf(m[rr], tmax);
            float alpha = __expf(m[rr] - mnew);
            m[rr] = mnew;
            float rsum = 0.f;
            #pragma unroll
            for (int cc = 0; cc < 4; cc++) {
                float p = __expf(S[rr][cc] - mnew);
                S[rr][cc] = p;
                rsum += p;
            }
            #pragma unroll
            for (int off = 1; off < 16; off <<= 1)
                rsum += __shfl_xor_sync(0xffffffffu, rsum, off);
            l[rr] = l[rr]*alpha + rsum;
            #pragma unroll
            for (int cc = 0; cc < 4; cc++) O[rr][cc] *= alpha;
        }

        __syncthreads();  // everyone done reading K from KsPt
        #pragma unroll
        for (int rr = 0; rr < 4; rr++)
            #pragma unroll
            for (int cc = 0; cc < 4; cc++)
                KsPt[(4*tx+cc)*65 + 4*ty+rr] = S[rr][cc];   // P^T
        __syncthreads();

        // O += P V
        #pragma unroll 8
        for (int c = 0; c < 64; c++) {
            float4 v4 = *(const float4*)&Vs[c*64 + 4*tx];
            float p[4];
            #pragma unroll
            for (int rr = 0; rr < 4; rr++) p[rr] = KsPt[c*65 + 4*ty+rr];
            #pragma unroll
            for (int rr = 0; rr < 4; rr++) {
                O[rr][0] = fmaf(p[rr], v4.x, O[rr][0]);
                O[rr][1] = fmaf(p[rr], v4.y, O[rr][1]);
                O[rr][2] = fmaf(p[rr], v4.z, O[rr][2]);
                O[rr][3] = fmaf(p[rr], v4.w, O[rr][3]);
            }
        }
    }

    // epilogue: divide by l, write (b, n, h*64+d)
    #pragma unroll
    for (int rr = 0; rr < 4; rr++) {
        float invl = 1.0f / l[rr];
        int n = i0 + 4*ty + rr;
        *(float4*)&g_att[((size_t)b*NN + n)*CC + h*HD + 4*tx] =
            make_float4(O[rr][0]*invl, O[rr][1]*invl, O[rr][2]*invl, O[rr][3]*invl);
    }
}

// ---------------- launch ----------------------------------------------------
extern "C" void kernel_launch(void* const* d_in, const int* in_sizes, int n_in,
                              void* d_out, int out_size)
{
    const float* x       = (const float*)d_in[0];
    const float* coords  = (const float*)d_in[1];
    const float* qkv_w   = (const float*)d_in[2];
    const float* proj_w  = (const float*)d_in[3];
    const float* proj_b  = (const float*)d_in[4];
    const float* mlp_w1  = (const float*)d_in[5];
    const float* mlp_b1  = (const float*)d_in[6];
    const float* mlp_w2  = (const float*)d_in[7];
    const float* mlp_b2  = (const float*)d_in[8];
    float* out = (float*)d_out;

    range_kernel<<<BB, 256>>>(coords);

    sgemm_kernel<<<dim3(18, 16), 256>>>(x, qkv_w, nullptr, nullptr, 0);

    bias_kernel<<<dim3(NN*NN/256, BB), 256>>>(coords, mlp_w1, mlp_b1, mlp_w2, mlp_b2);

    cudaFuncSetAttribute(attn_kernel,
                         cudaFuncAttributeMaxDynamicSharedMemorySize, 50176);
    attn_kernel<<<dim3(NN/64, HH, BB), 256, 49408>>>();

    sgemm_kernel<<<dim3(6, 16), 256>>>(nullptr, proj_w, proj_b, out, 1);
}